// round 1
// baseline (speedup 1.0000x reference)
#include <cuda_runtime.h>
#include <cstdint>

#define NBLK 128
#define NTHR 128
#define HID  512
#define BB   32
#define TT   32
#define INF_ 397
#define NOUT 129

// logits: 32*32*129 = 132096, h: 32*512, c: 32*512
#define LOGITS_ELEMS 132096
#define HC_ELEMS     16384

// smem layout (floats):
//  sW   : [0, 8192)            W_hh slice: 4 warps x 4 gates x 512
//  sh   : [8192, 8192+20480)   h staging [512][32] (16384) / precompute: latT(8192)+chT(12288)
//  sred : [28672, 28800)       4x32 cross-warp logits reduce
//  sidx : [28800, 28832)       argmax indices (int)
//  sE   : [28832, 28840)
#define SMEM_FLOATS 28840
#define SMEM_BYTES  (SMEM_FLOATS * 4)

__device__ float g_pre[TT * 2048 * BB];   // 8 MB: bias + latent + chord projections, [t][row][b]
__device__ float g_h[HID * BB];           // h, [k][b]
__device__ float g_th[HID * BB];          // tanh(h), [k][b]
__device__ unsigned g_arrive;
__device__ volatile unsigned g_epoch;

__device__ __forceinline__ float sigm(float x) { return 1.f / (1.f + __expf(-x)); }
__device__ __forceinline__ float tanh_p(float x) {
    float e = __expf(-2.f * fabsf(x));
    float r = (1.f - e) / (1.f + e);
    return copysignf(r, x);
}

__device__ __forceinline__ void gbar(unsigned target) {
    __syncthreads();
    if (threadIdx.x == 0) {
        __threadfence();
        unsigned prev = atomicAdd(&g_arrive, 1u);
        if (prev == NBLK - 1) {
            *(volatile unsigned*)&g_arrive = 0u;
            __threadfence();
            atomicAdd((unsigned*)&g_epoch, 1u);
        } else {
            while (g_epoch != target) { __nanosleep(32); }
            __threadfence();
        }
    }
    __syncthreads();
}

__global__ void __launch_bounds__(NTHR, 1)
decoder_kernel(const float* __restrict__ chords, const float* __restrict__ latent,
               const float* __restrict__ W_ih, const float* __restrict__ W_hh,
               const float* __restrict__ b_ih, const float* __restrict__ b_hh,
               const float* __restrict__ W_lin, const float* __restrict__ b_lin,
               float* __restrict__ out, int out_size)
{
    extern __shared__ float smem[];
    float* sW   = smem;                  // 8192
    float* sh   = smem + 8192;           // 20480
    float* sred = smem + 8192 + 20480;   // 128
    int*   sidx = (int*)(sred + 128);    // 32
    unsigned* sE = (unsigned*)(sidx + 32);

    const int tid  = threadIdx.x;
    const int lane = tid & 31;
    const int wid  = tid >> 5;
    const int bid  = blockIdx.x;
    const int j    = (bid << 2) + wid;   // hidden unit owned by this warp (0..511)

    if (tid == 0) sE[0] = g_epoch;       // epoch base for this launch

    // ---- Stage W_hh rows (i,f,g,o for unit j) into smem: persists all 32 steps ----
    {
        float* dst = sW + wid * 2048;
        #pragma unroll
        for (int g = 0; g < 4; ++g) {
            const float* src = W_hh + (size_t)(g * HID + j) * HID;
            for (int k = (lane << 2); k < 512; k += 128)
                *(float4*)(dst + g * 512 + k) = *(const float4*)(src + k);
        }
    }
    // ---- Transpose latent -> sh[l][b] (8192 floats) ----
    for (int i = tid; i < BB * 256; i += NTHR) {
        int b = i >> 8, l = i & 255;
        sh[l * 32 + b] = latent[i];
    }
    // ---- Transpose chords -> sh[8192 + (t*12+c)*32 + b] (12288 floats) ----
    {
        float* sch = sh + 8192;
        for (int i = tid; i < BB * TT * 12; i += NTHR) {
            int b = i / 384, rem = i - b * 384;
            sch[rem * 32 + b] = chords[i];
        }
    }
    __syncthreads();

    // ---- Precompute g_pre[t][row][b] = b_ih + b_hh + latent.W_ih + chords(t).W_ih ----
    {
        const float* sch = sh + 8192;
        #pragma unroll
        for (int g = 0; g < 4; ++g) {
            const int row = g * HID + j;
            const float* wrow = W_ih + (size_t)row * INF_;
            float acc = __ldg(b_ih + row) + __ldg(b_hh + row);
            #pragma unroll 8
            for (int k = 0; k < 256; ++k)
                acc = fmaf(sh[k * 32 + lane], __ldg(wrow + k), acc);
            float wc[12];
            #pragma unroll
            for (int cc = 0; cc < 12; ++cc) wc[cc] = __ldg(wrow + 385 + cc);
            for (int t = 0; t < TT; ++t) {
                float z = acc;
                #pragma unroll
                for (int cc = 0; cc < 12; ++cc)
                    z = fmaf(sch[(t * 12 + cc) * 32 + lane], wc[cc], z);
                g_pre[((size_t)(t * 2048) + row) * 32 + lane] = z;
            }
        }
    }
    __syncthreads();
    const unsigned ep0 = sE[0];
    unsigned nbar = 0;

    const int r0 = j, r1 = HID + j, r2 = 2 * HID + j, r3 = 3 * HID + j;
    const float* w0 = sW + wid * 2048;
    const float* w1 = w0 + 512;
    const float* w2 = w0 + 1024;
    const float* w3 = w0 + 1536;

    float creg = 0.f;   // cell state c[b=lane][j], lives in a register all 32 steps

    for (int t = 0; t < TT; ++t) {
        // ---- stage h[k][b] into smem (L2-coherent loads; other SMs wrote it) ----
        if (t > 0) {
            const float4* src4 = (const float4*)g_h;
            float4* dst4 = (float4*)sh;
            #pragma unroll 4
            for (int i = tid; i < HID * BB / 4; i += NTHR) dst4[i] = __ldcg(src4 + i);
        }
        __syncthreads();

        const float* prebase = g_pre + (size_t)(t * 2048) * 32;
        float zi = prebase[r0 * 32 + lane];
        float zf = prebase[r1 * 32 + lane];
        float zg = prebase[r2 * 32 + lane];
        float zo = prebase[r3 * 32 + lane];

        if (t > 0) {
            // one-hot prev contribution: a single W_ih column gather per gate row
            const int pidx = sidx[lane];
            zi += __ldg(W_ih + (size_t)r0 * INF_ + 256 + pidx);
            zf += __ldg(W_ih + (size_t)r1 * INF_ + 256 + pidx);
            zg += __ldg(W_ih + (size_t)r2 * INF_ + 256 + pidx);
            zo += __ldg(W_ih + (size_t)r3 * INF_ + 256 + pidx);

            // recurrent dot: 4 gate rows x 512, h from smem, W from smem (broadcast)
            float a0=0.f,b0v=0.f,a1=0.f,b1v=0.f,a2=0.f,b2v=0.f,a3=0.f,b3v=0.f;
            #pragma unroll 2
            for (int k = 0; k < 512; k += 4) {
                float4 W0 = *(const float4*)(w0 + k);
                float4 W1 = *(const float4*)(w1 + k);
                float4 W2 = *(const float4*)(w2 + k);
                float4 W3 = *(const float4*)(w3 + k);
                float h0 = sh[k * 32 + lane];
                float h1 = sh[k * 32 + 32 + lane];
                float h2 = sh[k * 32 + 64 + lane];
                float h3 = sh[k * 32 + 96 + lane];
                a0 = fmaf(W0.x, h0, a0); b0v = fmaf(W0.y, h1, b0v);
                a0 = fmaf(W0.z, h2, a0); b0v = fmaf(W0.w, h3, b0v);
                a1 = fmaf(W1.x, h0, a1); b1v = fmaf(W1.y, h1, b1v);
                a1 = fmaf(W1.z, h2, a1); b1v = fmaf(W1.w, h3, b1v);
                a2 = fmaf(W2.x, h0, a2); b2v = fmaf(W2.y, h1, b2v);
                a2 = fmaf(W2.z, h2, a2); b2v = fmaf(W2.w, h3, b2v);
                a3 = fmaf(W3.x, h0, a3); b3v = fmaf(W3.y, h1, b3v);
                a3 = fmaf(W3.z, h2, a3); b3v = fmaf(W3.w, h3, b3v);
            }
            zi += a0 + b0v; zf += a1 + b1v; zg += a2 + b2v; zo += a3 + b3v;
        }

        const float gi = sigm(zi), gf = sigm(zf), gg = tanh_p(zg), go = sigm(zo);
        creg = gf * creg + gi * gg;
        const float hv = go * tanh_p(creg);
        const float th = tanh_p(hv);
        g_h[j * 32 + lane]  = hv;
        g_th[j * 32 + lane] = th;
        if (t == TT - 1 && out_size >= LOGITS_ELEMS + 2 * HC_ELEMS) {
            out[LOGITS_ELEMS + lane * HID + j]            = hv;
            out[LOGITS_ELEMS + HC_ELEMS + lane * HID + j] = creg;
        }

        gbar(ep0 + (++nbar));   // h/th visible chip-wide

        // ---- logits: CTA `bid` computes output column o=bid (CTA 0 also o=128) ----
        {
            const int noutputs = (bid == 0) ? 2 : 1;
            for (int oo = 0; oo < noutputs; ++oo) {
                const int o = oo ? 128 : bid;
                const float* wl  = W_lin + (size_t)o * HID + wid * 128;
                const float* thp = g_th + (wid * 128) * 32;
                float acc = 0.f;
                #pragma unroll 8
                for (int k = 0; k < 128; ++k)
                    acc = fmaf(__ldcg(thp + k * 32 + lane), __ldg(wl + k), acc);
                sred[wid * 32 + lane] = acc;
                __syncthreads();
                if (wid == 0) {
                    float tot = sred[lane] + sred[32 + lane] + sred[64 + lane]
                              + sred[96 + lane] + __ldg(b_lin + o);
                    out[lane * (TT * NOUT) + t * NOUT + o] = tot;
                }
                __syncthreads();
            }
        }

        if (t < TT - 1) {
            gbar(ep0 + (++nbar));   // logits visible chip-wide
            // redundant per-CTA argmax (first-max tie-break, matching jnp.argmax)
            if (wid == 0) {
                const float* lp = out + lane * (TT * NOUT) + t * NOUT;
                float best = -3.4e38f; int bi = 0;
                for (int o = 0; o < NOUT; ++o) {
                    float v = __ldcg(lp + o);
                    if (v > best) { best = v; bi = o; }
                }
                sidx[lane] = bi;
            }
            // next iteration's stage + __syncthreads orders sidx before use
        }
    }
}

extern "C" void kernel_launch(void* const* d_in, const int* in_sizes, int n_in,
                              void* d_out, int out_size) {
    // Resolve inputs by element count (order-robust; b_ih/b_hh are interchangeable
    // since only their sum is used).
    const int want[8] = {12288, 8192, 813056, 1048576, 2048, 2048, 66048, 129};
    const float* p[8] = {nullptr, nullptr, nullptr, nullptr, nullptr, nullptr, nullptr, nullptr};
    bool used[64] = {false};
    for (int w = 0; w < 8; ++w) {
        for (int i = 0; i < n_in && i < 64; ++i) {
            if (!used[i] && in_sizes[i] == want[w]) {
                p[w] = (const float*)d_in[i];
                used[i] = true;
                break;
            }
        }
    }
    cudaFuncSetAttribute(decoder_kernel, cudaFuncAttributeMaxDynamicSharedMemorySize, SMEM_BYTES);
    decoder_kernel<<<NBLK, NTHR, SMEM_BYTES>>>(p[0], p[1], p[2], p[3], p[4], p[5], p[6], p[7],
                                               (float*)d_out, out_size);
}

// round 5
// speedup vs baseline: 1.4926x; 1.4926x over previous
#include <cuda_runtime.h>
#include <cstdint>

#define NBLK 128
#define NTHR 128
#define HID  512
#define BB   32
#define TT   32
#define INF_ 397
#define NOUT 129

// logits: 32*32*129 = 132096, h: 32*512, c: 32*512
#define LOGITS_ELEMS 132096
#define HC_ELEMS     16384

// smem layout (floats):
//  sW   : [0, 8192)            W_hh slice: 4 warps x 4 gates x 512
//  sh   : [8192, 8192+20480)   h staging [512][32] (16384) / precompute: latT(8192)+chT(12288)
//  sred : [28672, 28800)       4x32 cross-warp logits reduce
//  sidx : [28800, 28832)       argmax indices (int)
//  sE   : [28832, 28840)
#define SMEM_FLOATS 28840
#define SMEM_BYTES  (SMEM_FLOATS * 4)

__device__ float g_pre[TT * 2048 * BB];   // 8 MB: bias + latent + chord projections, [t][row][b]
__device__ float g_h[HID * BB];           // h, [k][b]
__device__ float g_th[HID * BB];          // tanh(h), [k][b]
__device__ unsigned g_arrive;
__device__ volatile unsigned g_epoch;

__device__ __forceinline__ float sigm(float x) { return 1.f / (1.f + __expf(-x)); }
__device__ __forceinline__ float tanh_p(float x) {
    float e = __expf(-2.f * fabsf(x));
    float r = (1.f - e) / (1.f + e);
    return copysignf(r, x);
}

__device__ __forceinline__ void gbar(unsigned target) {
    __syncthreads();
    if (threadIdx.x == 0) {
        __threadfence();
        unsigned prev = atomicAdd(&g_arrive, 1u);
        if (prev == NBLK - 1) {
            *(volatile unsigned*)&g_arrive = 0u;
            __threadfence();
            atomicAdd((unsigned*)&g_epoch, 1u);
        } else {
            while (g_epoch != target) { }
            __threadfence();
        }
    }
    __syncthreads();
}

__global__ void __launch_bounds__(NTHR, 1)
decoder_kernel(const float* __restrict__ chords, const float* __restrict__ latent,
               const float* __restrict__ W_ih, const float* __restrict__ W_hh,
               const float* __restrict__ b_ih, const float* __restrict__ b_hh,
               const float* __restrict__ W_lin, const float* __restrict__ b_lin,
               float* __restrict__ out, int out_size)
{
    extern __shared__ float smem[];
    float* sW   = smem;                  // 8192
    float* sh   = smem + 8192;           // 20480
    float* sred = smem + 8192 + 20480;   // 128
    int*   sidx = (int*)(sred + 128);    // 32
    unsigned* sE = (unsigned*)(sidx + 32);

    const int tid  = threadIdx.x;
    const int lane = tid & 31;
    const int wid  = tid >> 5;
    const int bid  = blockIdx.x;
    const int j    = (bid << 2) + wid;   // hidden unit owned by this warp (0..511)

    if (tid == 0) sE[0] = g_epoch;       // epoch base for this launch

    // ---- Stage W_hh rows (i,f,g,o for unit j) into smem: persists all 32 steps ----
    {
        float* dst = sW + wid * 2048;
        #pragma unroll
        for (int g = 0; g < 4; ++g) {
            const float* src = W_hh + (size_t)(g * HID + j) * HID;
            for (int k = (lane << 2); k < 512; k += 128)
                *(float4*)(dst + g * 512 + k) = *(const float4*)(src + k);
        }
    }
    // ---- Transpose latent -> sh[l][b] (8192 floats) ----
    for (int i = tid; i < BB * 256; i += NTHR) {
        int b = i >> 8, l = i & 255;
        sh[l * 32 + b] = latent[i];
    }
    // ---- Transpose chords -> sh[8192 + (t*12+c)*32 + b] (12288 floats) ----
    {
        float* sch = sh + 8192;
        for (int i = tid; i < BB * TT * 12; i += NTHR) {
            int b = i / 384, rem = i - b * 384;
            sch[rem * 32 + b] = chords[i];
        }
    }
    __syncthreads();

    // ---- Precompute g_pre[t][row][b] = b_ih + b_hh + latent.W_ih + chords(t).W_ih ----
    {
        const float* sch = sh + 8192;
        #pragma unroll
        for (int g = 0; g < 4; ++g) {
            const int row = g * HID + j;
            const float* wrow = W_ih + (size_t)row * INF_;
            float acc = __ldg(b_ih + row) + __ldg(b_hh + row);
            #pragma unroll 8
            for (int k = 0; k < 256; ++k)
                acc = fmaf(sh[k * 32 + lane], __ldg(wrow + k), acc);
            float wc[12];
            #pragma unroll
            for (int cc = 0; cc < 12; ++cc) wc[cc] = __ldg(wrow + 385 + cc);
            for (int t = 0; t < TT; ++t) {
                float z = acc;
                #pragma unroll
                for (int cc = 0; cc < 12; ++cc)
                    z = fmaf(sch[(t * 12 + cc) * 32 + lane], wc[cc], z);
                g_pre[((size_t)(t * 2048) + row) * 32 + lane] = z;
            }
        }
    }
    __syncthreads();
    const unsigned ep0 = sE[0];
    unsigned nbar = 0;

    const int r0 = j, r1 = HID + j, r2 = 2 * HID + j, r3 = 3 * HID + j;
    const float* w0 = sW + wid * 2048;
    const float* w1 = w0 + 512;
    const float* w2 = w0 + 1024;
    const float* w3 = w0 + 1536;

    float creg = 0.f;   // cell state c[b=lane][j], lives in a register all 32 steps

    for (int t = 0; t < TT; ++t) {
        // ---- stage h[k][b] into smem (L2-coherent loads; other SMs wrote it) ----
        if (t > 0) {
            const float4* src4 = (const float4*)g_h;
            float4* dst4 = (float4*)sh;
            #pragma unroll 4
            for (int i = tid; i < HID * BB / 4; i += NTHR) dst4[i] = __ldcg(src4 + i);
        }
        __syncthreads();

        const float* prebase = g_pre + (size_t)(t * 2048) * 32;
        float zi = prebase[r0 * 32 + lane];
        float zf = prebase[r1 * 32 + lane];
        float zg = prebase[r2 * 32 + lane];
        float zo = prebase[r3 * 32 + lane];

        if (t > 0) {
            // one-hot prev contribution: a single W_ih column gather per gate row
            const int pidx = sidx[lane];
            zi += __ldg(W_ih + (size_t)r0 * INF_ + 256 + pidx);
            zf += __ldg(W_ih + (size_t)r1 * INF_ + 256 + pidx);
            zg += __ldg(W_ih + (size_t)r2 * INF_ + 256 + pidx);
            zo += __ldg(W_ih + (size_t)r3 * INF_ + 256 + pidx);

            // recurrent dot: 4 gate rows x 512, h from smem, W from smem (broadcast)
            float a0=0.f,b0v=0.f,a1=0.f,b1v=0.f,a2=0.f,b2v=0.f,a3=0.f,b3v=0.f;
            #pragma unroll 2
            for (int k = 0; k < 512; k += 4) {
                float4 W0 = *(const float4*)(w0 + k);
                float4 W1 = *(const float4*)(w1 + k);
                float4 W2 = *(const float4*)(w2 + k);
                float4 W3 = *(const float4*)(w3 + k);
                float h0 = sh[k * 32 + lane];
                float h1 = sh[k * 32 + 32 + lane];
                float h2 = sh[k * 32 + 64 + lane];
                float h3 = sh[k * 32 + 96 + lane];
                a0 = fmaf(W0.x, h0, a0); b0v = fmaf(W0.y, h1, b0v);
                a0 = fmaf(W0.z, h2, a0); b0v = fmaf(W0.w, h3, b0v);
                a1 = fmaf(W1.x, h0, a1); b1v = fmaf(W1.y, h1, b1v);
                a1 = fmaf(W1.z, h2, a1); b1v = fmaf(W1.w, h3, b1v);
                a2 = fmaf(W2.x, h0, a2); b2v = fmaf(W2.y, h1, b2v);
                a2 = fmaf(W2.z, h2, a2); b2v = fmaf(W2.w, h3, b2v);
                a3 = fmaf(W3.x, h0, a3); b3v = fmaf(W3.y, h1, b3v);
                a3 = fmaf(W3.z, h2, a3); b3v = fmaf(W3.w, h3, b3v);
            }
            zi += a0 + b0v; zf += a1 + b1v; zg += a2 + b2v; zo += a3 + b3v;
        }

        const float gi = sigm(zi), gf = sigm(zf), gg = tanh_p(zg), go = sigm(zo);
        creg = gf * creg + gi * gg;
        const float hv = go * tanh_p(creg);
        const float th = tanh_p(hv);
        g_h[j * 32 + lane]  = hv;
        g_th[j * 32 + lane] = th;
        if (t == TT - 1 && out_size >= LOGITS_ELEMS + 2 * HC_ELEMS) {
            out[LOGITS_ELEMS + lane * HID + j]            = hv;
            out[LOGITS_ELEMS + HC_ELEMS + lane * HID + j] = creg;
        }

        gbar(ep0 + (++nbar));   // h/th visible chip-wide

        // ---- logits: CTA `bid` computes output column o=bid (CTA 0 also o=128) ----
        {
            const int noutputs = (bid == 0) ? 2 : 1;
            for (int oo = 0; oo < noutputs; ++oo) {
                const int o = oo ? 128 : bid;
                const float* wl  = W_lin + (size_t)o * HID + wid * 128;
                const float* thp = g_th + (wid * 128) * 32;
                float acc = 0.f;
                #pragma unroll 8
                for (int k = 0; k < 128; ++k)
                    acc = fmaf(__ldcg(thp + k * 32 + lane), __ldg(wl + k), acc);
                sred[wid * 32 + lane] = acc;
                __syncthreads();
                if (wid == 0) {
                    float tot = sred[lane] + sred[32 + lane] + sred[64 + lane]
                              + sred[96 + lane] + __ldg(b_lin + o);
                    out[lane * (TT * NOUT) + t * NOUT + o] = tot;
                }
                __syncthreads();
            }
        }

        if (t < TT - 1) {
            gbar(ep0 + (++nbar));   // logits visible chip-wide
            // parallel per-CTA argmax over the SAME out[] values as R1's serial scan.
            // warp `wid` handles batches b = wid*8 .. wid*8+7; 4 lanes per batch,
            // lane-group og = lane&3 scans o = og, og+4, ... (ascending -> first-max
            // within its stride class), then 4-lane reduce with strict-> + index
            // tie-break == global first-max == jnp.argmax. Bit-identical decisions.
            {
                const int b  = (wid << 3) + (lane >> 2);
                const int og = lane & 3;
                const float* lp = out + b * (TT * NOUT) + t * NOUT;
                float best = -3.4e38f; int bix = 0x7fffffff;
                for (int o = og; o < NOUT; o += 4) {
                    float v = __ldcg(lp + o);
                    if (v > best) { best = v; bix = o; }
                }
                #pragma unroll
                for (int off = 1; off <= 2; off <<= 1) {
                    float v = __shfl_xor_sync(0xffffffffu, best, off);
                    int   x = __shfl_xor_sync(0xffffffffu, bix,  off);
                    if (v > best || (v == best && x < bix)) { best = v; bix = x; }
                }
                if (og == 0) sidx[b] = bix;
            }
            // next iteration's stage + __syncthreads orders sidx before use
        }
    }
}

extern "C" void kernel_launch(void* const* d_in, const int* in_sizes, int n_in,
                              void* d_out, int out_size) {
    // Resolve inputs by element count (order-robust; b_ih/b_hh are interchangeable
    // since only their sum is used).
    const int want[8] = {12288, 8192, 813056, 1048576, 2048, 2048, 66048, 129};
    const float* p[8] = {nullptr, nullptr, nullptr, nullptr, nullptr, nullptr, nullptr, nullptr};
    bool used[64] = {false};
    for (int w = 0; w < 8; ++w) {
        for (int i = 0; i < n_in && i < 64; ++i) {
            if (!used[i] && in_sizes[i] == want[w]) {
                p[w] = (const float*)d_in[i];
                used[i] = true;
                break;
            }
        }
    }
    cudaFuncSetAttribute(decoder_kernel, cudaFuncAttributeMaxDynamicSharedMemorySize, SMEM_BYTES);
    decoder_kernel<<<NBLK, NTHR, SMEM_BYTES>>>(p[0], p[1], p[2], p[3], p[4], p[5], p[6], p[7],
                                               (float*)d_out, out_size);
}

// round 6
// speedup vs baseline: 1.9994x; 1.3396x over previous
#include <cuda_runtime.h>
#include <cstdint>

#define NBLK 128
#define NTHR 128
#define HID  512
#define BB   32
#define TT   32
#define INF_ 397
#define NOUT 129

// logits: 32*32*129 = 132096, h: 32*512, c: 32*512
#define LOGITS_ELEMS 132096
#define HC_ELEMS     16384

// smem layout (floats):
//  sW   : [0, 8192)            W_hh slice: 4 warps x 4 gates x 512
//  sh   : [8192, 8192+20480)   h staging [512][32] (16384) / precompute: latT(8192)+chT(12288)
//  sred : [28672, 28800)       4x32 cross-warp logits reduce
//  sidx : [28800, 28832)       argmax indices (int)
//  sE   : [28832, 28840)
#define SMEM_FLOATS 28840
#define SMEM_BYTES  (SMEM_FLOATS * 4)

__device__ float g_pre[TT * 2048 * BB];   // 8 MB: bias + latent + chord projections, [t][row][b]
__device__ float g_h[HID * BB];           // h, [k][b]
__device__ float g_th[HID * BB];          // tanh(h), [k][b]
__device__ __align__(128) unsigned g_arrive;   // monotonic across launches
__device__ __align__(128) unsigned g_epoch;    // monotonic across launches

__device__ __forceinline__ float sigm(float x) { return 1.f / (1.f + __expf(-x)); }
__device__ __forceinline__ float tanh_p(float x) {
    float e = __expf(-2.f * fabsf(x));
    float r = (1.f - e) / (1.f + e);
    return copysignf(r, x);
}

// Monotonic-counter global barrier.
// Invariant at every launch boundary: g_arrive == g_epoch * NBLK (each barrier
// adds NBLK arrives and exactly 1 epoch; launches are stream-ordered).
// target = absolute epoch value to reach. Arrive is a fire-and-forget
// red.release (pipelined at LTS, no 128 serialized read-modify-write round
// trips); only CTA 0 detects completion and releases the epoch.
__device__ __forceinline__ void gbar(unsigned target) {
    __syncthreads();
    if (threadIdx.x == 0) {
        __threadfence();
        asm volatile("red.release.gpu.global.add.u32 [%0], 1;"
                     :: "l"(&g_arrive) : "memory");
        if (blockIdx.x == 0) {
            const unsigned want = target * NBLK;
            unsigned a;
            do {
                asm volatile("ld.acquire.gpu.global.u32 %0, [%1];"
                             : "=r"(a) : "l"(&g_arrive) : "memory");
            } while ((int)(a - want) < 0);
            asm volatile("red.release.gpu.global.add.u32 [%0], 1;"
                         :: "l"(&g_epoch) : "memory");
        }
        unsigned e;
        do {
            asm volatile("ld.acquire.gpu.global.u32 %0, [%1];"
                         : "=r"(e) : "l"(&g_epoch) : "memory");
        } while ((int)(e - target) < 0);
        __threadfence();
    }
    __syncthreads();
}

__global__ void __launch_bounds__(NTHR, 1)
decoder_kernel(const float* __restrict__ chords, const float* __restrict__ latent,
               const float* __restrict__ W_ih, const float* __restrict__ W_hh,
               const float* __restrict__ b_ih, const float* __restrict__ b_hh,
               const float* __restrict__ W_lin, const float* __restrict__ b_lin,
               float* __restrict__ out, int out_size)
{
    extern __shared__ float smem[];
    float* sW   = smem;                  // 8192
    float* sh   = smem + 8192;           // 20480
    float* sred = smem + 8192 + 20480;   // 128
    int*   sidx = (int*)(sred + 128);    // 32
    unsigned* sE = (unsigned*)(sidx + 32);

    const int tid  = threadIdx.x;
    const int lane = tid & 31;
    const int wid  = tid >> 5;
    const int bid  = blockIdx.x;
    const int j    = (bid << 2) + wid;   // hidden unit owned by this warp (0..511)

    if (tid == 0) {
        unsigned e0;
        asm volatile("ld.acquire.gpu.global.u32 %0, [%1];"
                     : "=r"(e0) : "l"(&g_epoch) : "memory");
        sE[0] = e0;                      // epoch base for this launch
    }

    // ---- Stage W_hh rows (i,f,g,o for unit j) into smem: persists all 32 steps ----
    {
        float* dst = sW + wid * 2048;
        #pragma unroll
        for (int g = 0; g < 4; ++g) {
            const float* src = W_hh + (size_t)(g * HID + j) * HID;
            for (int k = (lane << 2); k < 512; k += 128)
                *(float4*)(dst + g * 512 + k) = *(const float4*)(src + k);
        }
    }
    // ---- Transpose latent -> sh[l][b] (8192 floats) ----
    for (int i = tid; i < BB * 256; i += NTHR) {
        int b = i >> 8, l = i & 255;
        sh[l * 32 + b] = latent[i];
    }
    // ---- Transpose chords -> sh[8192 + (t*12+c)*32 + b] (12288 floats) ----
    {
        float* sch = sh + 8192;
        for (int i = tid; i < BB * TT * 12; i += NTHR) {
            int b = i / 384, rem = i - b * 384;
            sch[rem * 32 + b] = chords[i];
        }
    }
    __syncthreads();

    // ---- Precompute g_pre[t][row][b] = b_ih + b_hh + latent.W_ih + chords(t).W_ih ----
    {
        const float* sch = sh + 8192;
        #pragma unroll
        for (int g = 0; g < 4; ++g) {
            const int row = g * HID + j;
            const float* wrow = W_ih + (size_t)row * INF_;
            float acc = __ldg(b_ih + row) + __ldg(b_hh + row);
            #pragma unroll 8
            for (int k = 0; k < 256; ++k)
                acc = fmaf(sh[k * 32 + lane], __ldg(wrow + k), acc);
            float wc[12];
            #pragma unroll
            for (int cc = 0; cc < 12; ++cc) wc[cc] = __ldg(wrow + 385 + cc);
            for (int t = 0; t < TT; ++t) {
                float z = acc;
                #pragma unroll
                for (int cc = 0; cc < 12; ++cc)
                    z = fmaf(sch[(t * 12 + cc) * 32 + lane], wc[cc], z);
                g_pre[((size_t)(t * 2048) + row) * 32 + lane] = z;
            }
        }
    }
    __syncthreads();
    const unsigned ep0 = sE[0];
    unsigned nbar = 0;

    const int r0 = j, r1 = HID + j, r2 = 2 * HID + j, r3 = 3 * HID + j;
    const float* w0 = sW + wid * 2048;
    const float* w1 = w0 + 512;
    const float* w2 = w0 + 1024;
    const float* w3 = w0 + 1536;

    float creg = 0.f;   // cell state c[b=lane][j], lives in a register all 32 steps

    for (int t = 0; t < TT; ++t) {
        // ---- stage h[k][b] into smem (L2-coherent loads; other SMs wrote it) ----
        if (t > 0) {
            const float4* src4 = (const float4*)g_h;
            float4* dst4 = (float4*)sh;
            #pragma unroll 4
            for (int i = tid; i < HID * BB / 4; i += NTHR) dst4[i] = __ldcg(src4 + i);
        }
        __syncthreads();

        const float* prebase = g_pre + (size_t)(t * 2048) * 32;
        float zi = prebase[r0 * 32 + lane];
        float zf = prebase[r1 * 32 + lane];
        float zg = prebase[r2 * 32 + lane];
        float zo = prebase[r3 * 32 + lane];

        if (t > 0) {
            // one-hot prev contribution: a single W_ih column gather per gate row
            const int pidx = sidx[lane];
            zi += __ldg(W_ih + (size_t)r0 * INF_ + 256 + pidx);
            zf += __ldg(W_ih + (size_t)r1 * INF_ + 256 + pidx);
            zg += __ldg(W_ih + (size_t)r2 * INF_ + 256 + pidx);
            zo += __ldg(W_ih + (size_t)r3 * INF_ + 256 + pidx);

            // recurrent dot: 4 gate rows x 512, h from smem, W from smem (broadcast)
            float a0=0.f,b0v=0.f,a1=0.f,b1v=0.f,a2=0.f,b2v=0.f,a3=0.f,b3v=0.f;
            #pragma unroll 2
            for (int k = 0; k < 512; k += 4) {
                float4 W0 = *(const float4*)(w0 + k);
                float4 W1 = *(const float4*)(w1 + k);
                float4 W2 = *(const float4*)(w2 + k);
                float4 W3 = *(const float4*)(w3 + k);
                float h0 = sh[k * 32 + lane];
                float h1 = sh[k * 32 + 32 + lane];
                float h2 = sh[k * 32 + 64 + lane];
                float h3 = sh[k * 32 + 96 + lane];
                a0 = fmaf(W0.x, h0, a0); b0v = fmaf(W0.y, h1, b0v);
                a0 = fmaf(W0.z, h2, a0); b0v = fmaf(W0.w, h3, b0v);
                a1 = fmaf(W1.x, h0, a1); b1v = fmaf(W1.y, h1, b1v);
                a1 = fmaf(W1.z, h2, a1); b1v = fmaf(W1.w, h3, b1v);
                a2 = fmaf(W2.x, h0, a2); b2v = fmaf(W2.y, h1, b2v);
                a2 = fmaf(W2.z, h2, a2); b2v = fmaf(W2.w, h3, b2v);
                a3 = fmaf(W3.x, h0, a3); b3v = fmaf(W3.y, h1, b3v);
                a3 = fmaf(W3.z, h2, a3); b3v = fmaf(W3.w, h3, b3v);
            }
            zi += a0 + b0v; zf += a1 + b1v; zg += a2 + b2v; zo += a3 + b3v;
        }

        const float gi = sigm(zi), gf = sigm(zf), gg = tanh_p(zg), go = sigm(zo);
        creg = gf * creg + gi * gg;
        const float hv = go * tanh_p(creg);
        const float th = tanh_p(hv);
        g_h[j * 32 + lane]  = hv;
        g_th[j * 32 + lane] = th;
        if (t == TT - 1 && out_size >= LOGITS_ELEMS + 2 * HC_ELEMS) {
            out[LOGITS_ELEMS + lane * HID + j]            = hv;
            out[LOGITS_ELEMS + HC_ELEMS + lane * HID + j] = creg;
        }

        gbar(ep0 + (++nbar));   // h/th visible chip-wide

        // ---- logits: CTA `bid` computes output column o=bid (CTA 0 also o=128) ----
        {
            const int noutputs = (bid == 0) ? 2 : 1;
            for (int oo = 0; oo < noutputs; ++oo) {
                const int o = oo ? 128 : bid;
                const float* wl  = W_lin + (size_t)o * HID + wid * 128;
                const float* thp = g_th + (wid * 128) * 32;
                // 4 independent accumulators, fully unrolled -> high MLP on the
                // L2 reads of g_th (the per-step logits latency bottleneck).
                float c0 = 0.f, c1 = 0.f, c2 = 0.f, c3 = 0.f;
                #pragma unroll
                for (int k = 0; k < 128; k += 4) {
                    c0 = fmaf(__ldcg(thp + (k + 0) * 32 + lane), __ldg(wl + k + 0), c0);
                    c1 = fmaf(__ldcg(thp + (k + 1) * 32 + lane), __ldg(wl + k + 1), c1);
                    c2 = fmaf(__ldcg(thp + (k + 2) * 32 + lane), __ldg(wl + k + 2), c2);
                    c3 = fmaf(__ldcg(thp + (k + 3) * 32 + lane), __ldg(wl + k + 3), c3);
                }
                sred[wid * 32 + lane] = (c0 + c1) + (c2 + c3);
                __syncthreads();
                if (wid == 0) {
                    float tot = sred[lane] + sred[32 + lane] + sred[64 + lane]
                              + sred[96 + lane] + __ldg(b_lin + o);
                    out[lane * (TT * NOUT) + t * NOUT + o] = tot;
                }
                __syncthreads();
            }
        }

        if (t < TT - 1) {
            gbar(ep0 + (++nbar));   // logits visible chip-wide
            // parallel per-CTA argmax: warp wid -> batches wid*8..wid*8+7,
            // 4 lanes per batch stride o by 4, reduce with strict-> + index
            // tie-break == global first-max == jnp.argmax.
            {
                const int b  = (wid << 3) + (lane >> 2);
                const int og = lane & 3;
                const float* lp = out + b * (TT * NOUT) + t * NOUT;
                float best = -3.4e38f; int bix = 0x7fffffff;
                for (int o = og; o < NOUT; o += 4) {
                    float v = __ldcg(lp + o);
                    if (v > best) { best = v; bix = o; }
                }
                #pragma unroll
                for (int off = 1; off <= 2; off <<= 1) {
                    float v = __shfl_xor_sync(0xffffffffu, best, off);
                    int   x = __shfl_xor_sync(0xffffffffu, bix,  off);
                    if (v > best || (v == best && x < bix)) { best = v; bix = x; }
                }
                if (og == 0) sidx[b] = bix;
            }
            // next iteration's stage + __syncthreads orders sidx before use
        }
    }
}

extern "C" void kernel_launch(void* const* d_in, const int* in_sizes, int n_in,
                              void* d_out, int out_size) {
    // Resolve inputs by element count (order-robust; b_ih/b_hh are interchangeable
    // since only their sum is used).
    const int want[8] = {12288, 8192, 813056, 1048576, 2048, 2048, 66048, 129};
    const float* p[8] = {nullptr, nullptr, nullptr, nullptr, nullptr, nullptr, nullptr, nullptr};
    bool used[64] = {false};
    for (int w = 0; w < 8; ++w) {
        for (int i = 0; i < n_in && i < 64; ++i) {
            if (!used[i] && in_sizes[i] == want[w]) {
                p[w] = (const float*)d_in[i];
                used[i] = true;
                break;
            }
        }
    }
    cudaFuncSetAttribute(decoder_kernel, cudaFuncAttributeMaxDynamicSharedMemorySize, SMEM_BYTES);
    decoder_kernel<<<NBLK, NTHR, SMEM_BYTES>>>(p[0], p[1], p[2], p[3], p[4], p[5], p[6], p[7],
                                               (float*)d_out, out_size);
}

// round 7
// speedup vs baseline: 2.1474x; 1.0740x over previous
#include <cuda_runtime.h>
#include <cstdint>

#define NBLK 128
#define NTHR 128
#define HID  512
#define BB   32
#define TT   32
#define INF_ 397
#define NOUT 129

// logits: 32*32*129 = 132096, h: 32*512, c: 32*512
#define LOGITS_ELEMS 132096
#define HC_ELEMS     16384

// smem layout (floats):
//  sW   : [0, 8192)            W_hh slice: 4 warps x 4 gates x 512
//  sh   : [8192, 8192+20480)   h staging [512][32] (16384) / precompute: latT(8192)+chT(12288)
//  sred : [28672, 28800)       4x32 cross-warp logits reduce
//  sidx : [28800, 28832)       argmax indices (int)
//  sE   : [28832, 28840)
#define SMEM_FLOATS 28840
#define SMEM_BYTES  (SMEM_FLOATS * 4)

__device__ float g_pre[TT * 2048 * BB];   // 8 MB: bias + latent + chord projections, [t][row][b]
__device__ float g_h[HID * BB];           // h, [k][b]
__device__ float g_th[HID * BB];          // tanh(h), [k][b]
__device__ __align__(128) unsigned g_arrive;   // monotonic across launches
__device__ __align__(128) unsigned g_epoch;    // monotonic; read only at launch start (stable base)

__device__ __forceinline__ float sigm(float x) { return 1.f / (1.f + __expf(-x)); }
__device__ __forceinline__ float tanh_p(float x) {
    float e = __expf(-2.f * fabsf(x));
    float r = (1.f - e) / (1.f + e);
    return copysignf(r, x);
}

// Direct-poll monotonic barrier.
// Invariants at launch boundaries: g_arrive == g_epoch * NBLK.
// Every CTA: red.release arrive, then acquire-poll g_arrive >= target*NBLK
// directly (no CTA0-detect/epoch hop on the critical path). CTA0 additionally
// bumps g_epoch once per barrier — consumed only as next launch's stable base
// (g_epoch cannot change between launch start and any CTA's first arrive,
// because barrier 1 needs all CTAs to arrive, and each reads g_epoch first).
__device__ __forceinline__ void gbar(unsigned target) {
    __syncthreads();
    if (threadIdx.x == 0) {
        __threadfence();
        asm volatile("red.release.gpu.global.add.u32 [%0], 1;"
                     :: "l"(&g_arrive) : "memory");
        const unsigned want = target * NBLK;
        unsigned a;
        do {
            asm volatile("ld.acquire.gpu.global.u32 %0, [%1];"
                         : "=r"(a) : "l"(&g_arrive) : "memory");
        } while ((int)(a - want) < 0);
        if (blockIdx.x == 0) {
            asm volatile("red.release.gpu.global.add.u32 [%0], 1;"
                         :: "l"(&g_epoch) : "memory");
        }
        __threadfence();
    }
    __syncthreads();
}

__global__ void __launch_bounds__(NTHR, 1)
decoder_kernel(const float* __restrict__ chords, const float* __restrict__ latent,
               const float* __restrict__ W_ih, const float* __restrict__ W_hh,
               const float* __restrict__ b_ih, const float* __restrict__ b_hh,
               const float* __restrict__ W_lin, const float* __restrict__ b_lin,
               float* __restrict__ out, int out_size)
{
    extern __shared__ float smem[];
    float* sW   = smem;                  // 8192
    float* sh   = smem + 8192;           // 20480
    float* sred = smem + 8192 + 20480;   // 128
    int*   sidx = (int*)(sred + 128);    // 32
    unsigned* sE = (unsigned*)(sidx + 32);

    const int tid  = threadIdx.x;
    const int lane = tid & 31;
    const int wid  = tid >> 5;
    const int bid  = blockIdx.x;
    const int j    = (bid << 2) + wid;   // hidden unit owned by this warp (0..511)

    if (tid == 0) {
        unsigned e0;
        asm volatile("ld.acquire.gpu.global.u32 %0, [%1];"
                     : "=r"(e0) : "l"(&g_epoch) : "memory");
        sE[0] = e0;                      // stable epoch base for this launch
    }

    // ---- Stage W_hh rows (i,f,g,o for unit j) into smem: persists all 32 steps ----
    {
        float* dst = sW + wid * 2048;
        #pragma unroll
        for (int g = 0; g < 4; ++g) {
            const float* src = W_hh + (size_t)(g * HID + j) * HID;
            for (int k = (lane << 2); k < 512; k += 128)
                *(float4*)(dst + g * 512 + k) = *(const float4*)(src + k);
        }
    }
    // ---- Transpose latent -> sh[l][b] (8192 floats) ----
    for (int i = tid; i < BB * 256; i += NTHR) {
        int b = i >> 8, l = i & 255;
        sh[l * 32 + b] = latent[i];
    }
    // ---- Transpose chords -> sh[8192 + (t*12+c)*32 + b] (12288 floats) ----
    {
        float* sch = sh + 8192;
        for (int i = tid; i < BB * TT * 12; i += NTHR) {
            int b = i / 384, rem = i - b * 384;
            sch[rem * 32 + b] = chords[i];
        }
    }
    __syncthreads();

    // ---- Precompute g_pre[t][row][b] = b_ih + b_hh + latent.W_ih + chords(t).W_ih ----
    {
        const float* sch = sh + 8192;
        #pragma unroll
        for (int g = 0; g < 4; ++g) {
            const int row = g * HID + j;
            const float* wrow = W_ih + (size_t)row * INF_;
            float acc = __ldg(b_ih + row) + __ldg(b_hh + row);
            #pragma unroll 8
            for (int k = 0; k < 256; ++k)
                acc = fmaf(sh[k * 32 + lane], __ldg(wrow + k), acc);
            float wc[12];
            #pragma unroll
            for (int cc = 0; cc < 12; ++cc) wc[cc] = __ldg(wrow + 385 + cc);
            for (int t = 0; t < TT; ++t) {
                float z = acc;
                #pragma unroll
                for (int cc = 0; cc < 12; ++cc)
                    z = fmaf(sch[(t * 12 + cc) * 32 + lane], wc[cc], z);
                g_pre[((size_t)(t * 2048) + row) * 32 + lane] = z;
            }
        }
    }
    __syncthreads();
    const unsigned ep0 = sE[0];
    unsigned nbar = 0;

    const int r0 = j, r1 = HID + j, r2 = 2 * HID + j, r3 = 3 * HID + j;
    const float* w0 = sW + wid * 2048;
    const float* w1 = w0 + 512;
    const float* w2 = w0 + 1024;
    const float* w3 = w0 + 1536;

    float creg = 0.f;   // cell state c[b=lane][j], lives in a register all 32 steps

    for (int t = 0; t < TT; ++t) {
        // sh holds h(t-1) staged at the END of the previous step (pre-barB hoist).
        __syncthreads();   // drains the hoisted STS; orders sidx writes too

        const float* prebase = g_pre + (size_t)(t * 2048) * 32;
        float zi = prebase[r0 * 32 + lane];
        float zf = prebase[r1 * 32 + lane];
        float zg = prebase[r2 * 32 + lane];
        float zo = prebase[r3 * 32 + lane];

        if (t > 0) {
            // one-hot prev contribution: a single W_ih column gather per gate row
            const int pidx = sidx[lane];
            zi += __ldg(W_ih + (size_t)r0 * INF_ + 256 + pidx);
            zf += __ldg(W_ih + (size_t)r1 * INF_ + 256 + pidx);
            zg += __ldg(W_ih + (size_t)r2 * INF_ + 256 + pidx);
            zo += __ldg(W_ih + (size_t)r3 * INF_ + 256 + pidx);

            // recurrent dot: 4 gate rows x 512, h from smem, W from smem (broadcast)
            float a0=0.f,b0v=0.f,a1=0.f,b1v=0.f,a2=0.f,b2v=0.f,a3=0.f,b3v=0.f;
            #pragma unroll 2
            for (int k = 0; k < 512; k += 4) {
                float4 W0 = *(const float4*)(w0 + k);
                float4 W1 = *(const float4*)(w1 + k);
                float4 W2 = *(const float4*)(w2 + k);
                float4 W3 = *(const float4*)(w3 + k);
                float h0 = sh[k * 32 + lane];
                float h1 = sh[k * 32 + 32 + lane];
                float h2 = sh[k * 32 + 64 + lane];
                float h3 = sh[k * 32 + 96 + lane];
                a0 = fmaf(W0.x, h0, a0); b0v = fmaf(W0.y, h1, b0v);
                a0 = fmaf(W0.z, h2, a0); b0v = fmaf(W0.w, h3, b0v);
                a1 = fmaf(W1.x, h0, a1); b1v = fmaf(W1.y, h1, b1v);
                a1 = fmaf(W1.z, h2, a1); b1v = fmaf(W1.w, h3, b1v);
                a2 = fmaf(W2.x, h0, a2); b2v = fmaf(W2.y, h1, b2v);
                a2 = fmaf(W2.z, h2, a2); b2v = fmaf(W2.w, h3, b2v);
                a3 = fmaf(W3.x, h0, a3); b3v = fmaf(W3.y, h1, b3v);
                a3 = fmaf(W3.z, h2, a3); b3v = fmaf(W3.w, h3, b3v);
            }
            zi += a0 + b0v; zf += a1 + b1v; zg += a2 + b2v; zo += a3 + b3v;
        }

        const float gi = sigm(zi), gf = sigm(zf), gg = tanh_p(zg), go = sigm(zo);
        creg = gf * creg + gi * gg;
        const float hv = go * tanh_p(creg);
        const float th = tanh_p(hv);
        g_h[j * 32 + lane]  = hv;
        g_th[j * 32 + lane] = th;
        if (t == TT - 1 && out_size >= LOGITS_ELEMS + 2 * HC_ELEMS) {
            out[LOGITS_ELEMS + lane * HID + j]            = hv;
            out[LOGITS_ELEMS + HC_ELEMS + lane * HID + j] = creg;
        }

        gbar(ep0 + (++nbar));   // barA: h(t)/th(t) visible chip-wide

        // ---- logits: CTA `bid` computes output column o=bid (CTA 0 also o=128) ----
        {
            const int noutputs = (bid == 0) ? 2 : 1;
            for (int oo = 0; oo < noutputs; ++oo) {
                const int o = oo ? 128 : bid;
                const float* wl  = W_lin + (size_t)o * HID + wid * 128;
                const float* thp = g_th + (wid * 128) * 32;
                float c0 = 0.f, c1 = 0.f, c2 = 0.f, c3 = 0.f;
                #pragma unroll
                for (int k = 0; k < 128; k += 4) {
                    c0 = fmaf(__ldcg(thp + (k + 0) * 32 + lane), __ldg(wl + k + 0), c0);
                    c1 = fmaf(__ldcg(thp + (k + 1) * 32 + lane), __ldg(wl + k + 1), c1);
                    c2 = fmaf(__ldcg(thp + (k + 2) * 32 + lane), __ldg(wl + k + 2), c2);
                    c3 = fmaf(__ldcg(thp + (k + 3) * 32 + lane), __ldg(wl + k + 3), c3);
                }
                sred[wid * 32 + lane] = (c0 + c1) + (c2 + c3);
                __syncthreads();
                if (wid == 0) {
                    float tot = sred[lane] + sred[32 + lane] + sred[64 + lane]
                              + sred[96 + lane] + __ldg(b_lin + o);
                    out[lane * (TT * NOUT) + t * NOUT + o] = tot;
                }
                __syncthreads();
            }
        }

        if (t < TT - 1) {
            // ---- HOISTED stage of h(t) for step t+1, issued BEFORE barB ----
            // g_h holds h(t) stably from barA(t) until some CTA passes barB(t);
            // since barB can't complete before this CTA arrives, these reads are
            // race-free, and their latency overlaps the barB wait + argmax.
            {
                const float4* src4 = (const float4*)g_h;
                float4* dst4 = (float4*)sh;
                #pragma unroll 4
                for (int i = tid; i < HID * BB / 4; i += NTHR) dst4[i] = __ldcg(src4 + i);
            }

            gbar(ep0 + (++nbar));   // barB: logits visible chip-wide

            // parallel per-CTA argmax: warp wid -> batches wid*8..wid*8+7,
            // 4 lanes per batch stride o by 4, reduce with strict-> + index
            // tie-break == global first-max == jnp.argmax.
            {
                const int b  = (wid << 3) + (lane >> 2);
                const int og = lane & 3;
                const float* lp = out + b * (TT * NOUT) + t * NOUT;
                float best = -3.4e38f; int bix = 0x7fffffff;
                for (int o = og; o < NOUT; o += 4) {
                    float v = __ldcg(lp + o);
                    if (v > best) { best = v; bix = o; }
                }
                #pragma unroll
                for (int off = 1; off <= 2; off <<= 1) {
                    float v = __shfl_xor_sync(0xffffffffu, best, off);
                    int   x = __shfl_xor_sync(0xffffffffu, bix,  off);
                    if (v > best || (v == best && x < bix)) { best = v; bix = x; }
                }
                if (og == 0) sidx[b] = bix;
            }
            // loop-top __syncthreads orders the staged sh + sidx before use
        }
    }
}

extern "C" void kernel_launch(void* const* d_in, const int* in_sizes, int n_in,
                              void* d_out, int out_size) {
    // Resolve inputs by element count (order-robust; b_ih/b_hh are interchangeable
    // since only their sum is used).
    const int want[8] = {12288, 8192, 813056, 1048576, 2048, 2048, 66048, 129};
    const float* p[8] = {nullptr, nullptr, nullptr, nullptr, nullptr, nullptr, nullptr, nullptr};
    bool used[64] = {false};
    for (int w = 0; w < 8; ++w) {
        for (int i = 0; i < n_in && i < 64; ++i) {
            if (!used[i] && in_sizes[i] == want[w]) {
                p[w] = (const float*)d_in[i];
                used[i] = true;
                break;
            }
        }
    }
    cudaFuncSetAttribute(decoder_kernel, cudaFuncAttributeMaxDynamicSharedMemorySize, SMEM_BYTES);
    decoder_kernel<<<NBLK, NTHR, SMEM_BYTES>>>(p[0], p[1], p[2], p[3], p[4], p[5], p[6], p[7],
                                               (float*)d_out, out_size);
}